// round 15
// baseline (speedup 1.0000x reference)
#include <cuda_runtime.h>
#include <cuda_fp16.h>
#include <mma.h>
#include <cstdint>

using namespace nvcuda;

#define H 128
#define NI_MAX 100000
#define NT_MAX 100000
#define E_MAX  800000
#define SCAN_B 1024
#define WLD 132      // epilogue C smem ld (floats)
#define WLDH 136     // W smem ld (halves)
#define XPADH 40     // x smem tile ld (halves)

// ---------------- scratch (device globals; no allocation allowed) ----------
__device__ uint2    g_hh[(size_t)NI_MAX * 32];   // h_src fp16 [NI,128]
__device__ uint2    g_aggh[(size_t)NT_MAX * 32]; // agg fp16 [NT,128]
__device__ float    g_asrc[NI_MAX];
__device__ float    g_adst[NT_MAX];
__device__ int      g_rank[E_MAX];             // per-edge rank within dst segment
__device__ int      g_cnt[NT_MAX];
__device__ int      g_off[NT_MAX];
__device__ int      g_itmp[NT_MAX];            // inclusive scan temp
__device__ int      g_bsum[256];
__device__ int2     g_edge[E_MAX];             // CSR payload {src, ev bits}
__device__ float4   g_wvd[32];                 // W_taste^T @ att_dst
__device__ float4   g_wvs[32];                 // W_ing^T @ att_src
__device__ float    g_cd[1];                   // b_taste . att_dst
__device__ float    g_cs[1];                   // b_ing . att_src
__device__ float    g_csum[H];
__device__ float    g_csq[H];
__device__ float4   g_scale[32];
__device__ float4   g_shift[32];
__device__ int      g_tick[1];

// ---------------- host-side streams/events (created pre-main) --------------
struct SideStreams {
    cudaStream_t s1, s2;
    cudaEvent_t evF, evA, evB;
    SideStreams() {
        cudaStreamCreateWithFlags(&s1, cudaStreamNonBlocking);
        cudaStreamCreateWithFlags(&s2, cudaStreamNonBlocking);
        cudaEventCreateWithFlags(&evF, cudaEventDisableTiming);
        cudaEventCreateWithFlags(&evA, cudaEventDisableTiming);
        cudaEventCreateWithFlags(&evB, cudaEventDisableTiming);
    }
};
static SideStreams g_ss;

// ---------------- K0a: zero per-call state ---------------------------------
__global__ void k_zero(int nt) {
    int i = blockIdx.x * blockDim.x + threadIdx.x;
    if (i < nt) g_cnt[i] = 0;
    if (i < H) {
        g_csum[i] = 0.f;
        g_csq[i]  = 0.f;
    }
    if (i == 0) g_tick[0] = 0;
}

// ---------------- K0b: both attention matvec preps -------------------------
// t<128: wv_dst = W_taste^T attd, c_dst = b_taste.attd
// t>=128: wv_src = W_ing^T atts,  c_src = b_ing.atts
__global__ void k_prep(const float* __restrict__ Wt_, const float* __restrict__ bt,
                       const float* __restrict__ attd,
                       const float* __restrict__ Wi_, const float* __restrict__ bi,
                       const float* __restrict__ atts) {
    __shared__ float sh[256];
    int t = threadIdx.x;                       // 256 threads
    if (t < H) {
        float s = 0.f;
        #pragma unroll 8
        for (int k = 0; k < H; k++) s += Wt_[k * H + t] * attd[k];
        ((float*)g_wvd)[t] = s;
        sh[t] = bt[t] * attd[t];
    } else {
        int c = t - H;
        float s = 0.f;
        #pragma unroll 8
        for (int k = 0; k < H; k++) s += Wi_[k * H + c] * atts[k];
        ((float*)g_wvs)[c] = s;
        sh[t] = bi[c] * atts[c];
    }
    __syncthreads();
    for (int o = 64; o > 0; o >>= 1) {
        if (t < o) sh[t] += sh[t + o];
        if (t >= H && t < H + o) sh[t] += sh[t + o];
        __syncthreads();
    }
    if (t == 0) g_cd[0] = sh[0];
    if (t == H) g_cs[0] = sh[H];
}

// ---------------- K2: a = x @ wv + c  (8 nodes/warp) ------------------------
// which=0 -> g_adst (wvd,cd) ; which=1 -> g_asrc (wvs,cs)
__global__ void k_attvec(const float* __restrict__ x, int n, int which) {
    int wid  = blockIdx.x * (blockDim.x >> 5) + (threadIdx.x >> 5);
    int lane = threadIdx.x & 31;
    int t0 = wid * 8;
    if (t0 >= n) return;
    float4 w = which ? g_wvs[lane] : g_wvd[lane];
    float* out = which ? g_asrc : g_adst;
    float d[8];
    #pragma unroll
    for (int j = 0; j < 8; j++) {
        int t = t0 + j;
        d[j] = 0.f;
        if (t < n) {
            float4 v = ((const float4*)x)[(size_t)t * 32 + lane];
            d[j] = v.x * w.x + v.y * w.y + v.z * w.z + v.w * w.w;
        }
    }
    #pragma unroll
    for (int o = 16; o > 0; o >>= 1) {
        #pragma unroll
        for (int j = 0; j < 8; j++)
            d[j] += __shfl_xor_sync(0xFFFFFFFFu, d[j], o);
    }
    if (lane == 0) {
        float c = which ? g_cs[0] : g_cd[0];
        #pragma unroll
        for (int j = 0; j < 8; j++)
            if (t0 + j < n) out[t0 + j] = d[j] + c;
    }
}

// ---------------- K1: h = x @ W^T + b via FP16 wmma (chunked, dbl-buf) -----
__global__ __launch_bounds__(256, 2) void k_hsrc(
    const float* __restrict__ x, const float* __restrict__ W,
    const float* __restrict__ b, int ni) {
    extern __shared__ float sm[];
    __half* smw = (__half*)sm;                 // W half: [col c][k] c*WLDH+k (34.8KB)
    __half* smx = (__half*)sm + H * WLDH;      // x half: [row][XPADH] (10.2KB)

    for (int i = threadIdx.x; i < H * H / 2; i += 256) {
        float2 w2 = ((const float2*)W)[i];
        int c = (i * 2) >> 7, k = (i * 2) & 127;
        *(__half2*)(smw + c * WLDH + k) = __floats2half2_rn(w2.x, w2.y);
    }

    int warp = threadIdx.x >> 5;
    int lane = threadIdx.x & 31;
    int r0 = blockIdx.x * 128;
    if (r0 + 128 > ni) r0 = ni - 128;          // tail overlap
    int rloc = warp * 16;

    uint2 reg[4];
    #pragma unroll
    for (int i = 0; i < 4; i++) {
        int idx = threadIdx.x + i * 256;
        int row = idx >> 3, c4 = idx & 7;
        float4 v = *(const float4*)(x + (size_t)(r0 + row) * H + c4 * 4);
        __half2 h0 = __floats2half2_rn(v.x, v.y);
        __half2 h1 = __floats2half2_rn(v.z, v.w);
        reg[i].x = *reinterpret_cast<unsigned*>(&h0);
        reg[i].y = *reinterpret_cast<unsigned*>(&h1);
    }
    #pragma unroll
    for (int i = 0; i < 4; i++) {
        int idx = threadIdx.x + i * 256;
        int row = idx >> 3, c4 = idx & 7;
        *(uint2*)(smx + row * XPADH + c4 * 4) = reg[i];
    }
    __syncthreads();

    wmma::fragment<wmma::accumulator, 16, 16, 16, float> c[8];
    #pragma unroll
    for (int j = 0; j < 8; j++) wmma::fill_fragment(c[j], 0.f);

    for (int kc = 0; kc < 4; kc++) {
        if (kc < 3) {
            #pragma unroll
            for (int i = 0; i < 4; i++) {
                int idx = threadIdx.x + i * 256;
                int row = idx >> 3, c4 = idx & 7;
                float4 v = *(const float4*)(x + (size_t)(r0 + row) * H + (kc + 1) * 32 + c4 * 4);
                __half2 h0 = __floats2half2_rn(v.x, v.y);
                __half2 h1 = __floats2half2_rn(v.z, v.w);
                reg[i].x = *reinterpret_cast<unsigned*>(&h0);
                reg[i].y = *reinterpret_cast<unsigned*>(&h1);
            }
        }
        #pragma unroll
        for (int kk = 0; kk < 32; kk += 16) {
            wmma::fragment<wmma::matrix_a, 16, 16, 16, __half, wmma::row_major> a;
            wmma::load_matrix_sync(a, smx + rloc * XPADH + kk, XPADH);
            #pragma unroll
            for (int j = 0; j < 8; j++) {
                wmma::fragment<wmma::matrix_b, 16, 16, 16, __half, wmma::col_major> bf;
                wmma::load_matrix_sync(bf, smw + (j * 16) * WLDH + kc * 32 + kk, WLDH);
                wmma::mma_sync(c[j], a, bf, c[j]);
            }
        }
        __syncthreads();
        if (kc < 3) {
            #pragma unroll
            for (int i = 0; i < 4; i++) {
                int idx = threadIdx.x + i * 256;
                int row = idx >> 3, c4 = idx & 7;
                *(uint2*)(smx + row * XPADH + c4 * 4) = reg[i];
            }
            __syncthreads();
        }
    }

    float* cs = sm + rloc * WLD;
    #pragma unroll
    for (int j = 0; j < 8; j++)
        wmma::store_matrix_sync(cs + j * 16, c[j], WLD, wmma::mem_row_major);
    __syncwarp();

    float4 bv = ((const float4*)b)[lane];
    for (int rr = 0; rr < 16; rr++) {
        int r = r0 + rloc + rr;
        float4 v = *(float4*)(cs + rr * WLD + lane * 4);
        v.x += bv.x; v.y += bv.y; v.z += bv.z; v.w += bv.w;
        __half2 p0 = __floats2half2_rn(v.x, v.y);
        __half2 p1 = __floats2half2_rn(v.z, v.w);
        uint2 pk;
        pk.x = *reinterpret_cast<unsigned*>(&p0);
        pk.y = *reinterpret_cast<unsigned*>(&p1);
        g_hh[(size_t)r * 32 + lane] = pk;
    }
}

// ---------------- K3: per-edge rank only (single atomic, no gathers) -------
__global__ void k_edge(const int* __restrict__ ei, int E_, int ni, int nt) {
    int e = blockIdx.x * blockDim.x + threadIdx.x;
    if (e >= E_) return;
    int s = ei[e];
    int d = ei[E_ + e];
    if ((unsigned)s >= (unsigned)ni || (unsigned)d >= (unsigned)nt) return;  // guard
    g_rank[e] = atomicAdd(&g_cnt[d], 1);
}

// ---------------- scan (counting-sort offsets) -----------------------------
__global__ void k_scan1(int n) {
    __shared__ int sh[SCAN_B];
    int i = blockIdx.x * SCAN_B + threadIdx.x;
    int v = (i < n) ? g_cnt[i] : 0;
    sh[threadIdx.x] = v;
    __syncthreads();
    for (int o = 1; o < SCAN_B; o <<= 1) {
        int t = (threadIdx.x >= o) ? sh[threadIdx.x - o] : 0;
        __syncthreads();
        sh[threadIdx.x] += t;
        __syncthreads();
    }
    if (i < n) g_itmp[i] = sh[threadIdx.x];
    if (threadIdx.x == SCAN_B - 1) g_bsum[blockIdx.x] = sh[threadIdx.x];
}
__global__ void k_scan3(int n, int nb) {
    __shared__ int sb[256];
    int t = threadIdx.x;
    if (t < 256) sb[t] = (t < nb) ? g_bsum[t] : 0;
    __syncthreads();
    for (int o = 1; o < 256; o <<= 1) {
        int x = 0;
        if (t < 256 && t >= o) x = sb[t - o];
        __syncthreads();
        if (t < 256) sb[t] += x;
        __syncthreads();
    }
    int boff = (blockIdx.x > 0) ? sb[blockIdx.x - 1] : 0;
    int i = blockIdx.x * SCAN_B + t;
    if (i < n) g_off[i] = g_itmp[i] - g_cnt[i] + boff;
}

// ---------------- K5: scatter into CSR; compute ev inline ------------------
__global__ void k_scatter(const int* __restrict__ ei, int E_, int ni, int nt) {
    int e = blockIdx.x * blockDim.x + threadIdx.x;
    if (e >= E_) return;
    int s = ei[e];
    int d = ei[E_ + e];
    if ((unsigned)s >= (unsigned)ni || (unsigned)d >= (unsigned)nt) return;  // guard
    float al = g_asrc[s] + g_adst[d];
    al = al > 0.f ? al : 0.2f * al;
    float ev = __expf(al);
    int pos = g_off[d] + g_rank[e];
    g_edge[pos] = make_int2(s, __float_as_int(ev));
}

// ---------------- K6: agg = relu(Σev·h / Σev) -> fp16; stats; BN prep ------
__global__ __launch_bounds__(256) void k_agg(int nt,
        const float* __restrict__ gamma, const float* __restrict__ beta, float invn) {
    __shared__ float bs[H], bq[H];
    __shared__ bool last;
    int tid  = threadIdx.x;
    if (tid < H) { bs[tid] = 0.f; bq[tid] = 0.f; }
    __syncthreads();

    int wid  = blockIdx.x * 8 + (tid >> 5);
    int lane = tid & 31;
    float4 acc = make_float4(0.f, 0.f, 0.f, 0.f);
    if (wid < nt) {
        int n = g_cnt[wid], off = g_off[wid];
        if (n > 0) {
            float den = 0.f;
            int2 pe = g_edge[off];
            uint2 p = g_hh[(size_t)pe.x * 32 + lane];
            for (int j = 0; j < n; j++) {
                int2 pe2 = make_int2(0, 0);
                uint2 p2 = make_uint2(0u, 0u);
                if (j + 1 < n) {
                    pe2 = g_edge[off + j + 1];
                    p2 = g_hh[(size_t)pe2.x * 32 + lane];   // issued before consume
                }
                __half2 h01 = *reinterpret_cast<__half2*>(&p.x);
                __half2 h23 = *reinterpret_cast<__half2*>(&p.y);
                float2 f01 = __half22float2(h01);
                float2 f23 = __half22float2(h23);
                float w = __int_as_float(pe.y);
                den += w;
                acc.x += w * f01.x; acc.y += w * f01.y;
                acc.z += w * f23.x; acc.w += w * f23.y;
                pe = pe2; p = p2;
            }
            float dinv = 1.0f / den;
            acc.x *= dinv; acc.y *= dinv; acc.z *= dinv; acc.w *= dinv;
        }
        acc.x = fmaxf(acc.x, 0.f); acc.y = fmaxf(acc.y, 0.f);
        acc.z = fmaxf(acc.z, 0.f); acc.w = fmaxf(acc.w, 0.f);
        __half2 p0 = __floats2half2_rn(acc.x, acc.y);
        __half2 p1 = __floats2half2_rn(acc.z, acc.w);
        uint2 pk;
        pk.x = *reinterpret_cast<unsigned*>(&p0);
        pk.y = *reinterpret_cast<unsigned*>(&p1);
        g_aggh[(size_t)wid * 32 + lane] = pk;
    }
    int c0 = lane * 4;
    atomicAdd(&bs[c0 + 0], acc.x); atomicAdd(&bs[c0 + 1], acc.y);
    atomicAdd(&bs[c0 + 2], acc.z); atomicAdd(&bs[c0 + 3], acc.w);
    atomicAdd(&bq[c0 + 0], acc.x * acc.x); atomicAdd(&bq[c0 + 1], acc.y * acc.y);
    atomicAdd(&bq[c0 + 2], acc.z * acc.z); atomicAdd(&bq[c0 + 3], acc.w * acc.w);
    __syncthreads();
    if (tid < H) {
        atomicAdd(&g_csum[tid], bs[tid]);
        atomicAdd(&g_csq[tid], bq[tid]);
    }
    __threadfence();
    if (tid == 0) last = (atomicAdd(&g_tick[0], 1) == gridDim.x - 1);
    __syncthreads();
    if (last && tid < H) {
        float mu  = g_csum[tid] * invn;
        float var = fmaxf(g_csq[tid] * invn - mu * mu, 0.f);
        float rs  = rsqrtf(var + 1e-5f);
        float sc  = gamma[tid] * rs;
        ((float*)g_scale)[tid] = sc;
        ((float*)g_shift)[tid] = beta[tid] - mu * sc;
    }
}

// ---------------- K9: out = relu(aggh*scale + shift) ------------------------
__global__ void k_bn(float* __restrict__ out, int nt) {
    int i = blockIdx.x * blockDim.x + threadIdx.x;     // (node,lane) index
    if (i >= nt * 32) return;
    int lane = i & 31;
    uint2 p = g_aggh[i];
    __half2 h01 = *reinterpret_cast<__half2*>(&p.x);
    __half2 h23 = *reinterpret_cast<__half2*>(&p.y);
    float2 f01 = __half22float2(h01);
    float2 f23 = __half22float2(h23);
    float4 sc = g_scale[lane];
    float4 sh = g_shift[lane];
    float4 v;
    v.x = fmaxf(f01.x * sc.x + sh.x, 0.f);
    v.y = fmaxf(f01.y * sc.y + sh.y, 0.f);
    v.z = fmaxf(f23.x * sc.z + sh.z, 0.f);
    v.w = fmaxf(f23.y * sc.w + sh.w, 0.f);
    ((float4*)out)[i] = v;
}

// ---------------- host -----------------------------------------------------
extern "C" void kernel_launch(void* const* d_in, const int* in_sizes, int n_in,
                              void* d_out, int out_size) {
    const float* x_ing   = (const float*)d_in[0];
    const float* x_taste = (const float*)d_in[1];
    const int*   ei      = (const int*)d_in[2];          // int32 edge index
    const float* W_ing   = (const float*)d_in[3];
    const float* b_ing   = (const float*)d_in[4];
    const float* W_taste = (const float*)d_in[5];
    const float* b_taste = (const float*)d_in[6];
    const float* att_src = (const float*)d_in[7];
    const float* att_dst = (const float*)d_in[8];
    // d_in[9..11] = k_lin_W, k_lin_b, q — unused (softmax over 1 metapath == 1.0)
    const float* gamma   = (const float*)d_in[12];
    const float* beta    = (const float*)d_in[13];

    int ni = in_sizes[0] / H;
    int nt = in_sizes[1] / H;
    int E_ = in_sizes[2] / 2;
    float* out = (float*)d_out;

    const int smemB = H * WLD * 4;   // 67.6 KB
    cudaFuncSetAttribute(k_hsrc, cudaFuncAttributeMaxDynamicSharedMemorySize, smemB);

    // fork: three independent chains
    cudaEventRecord(g_ss.evF, 0);
    cudaStreamWaitEvent(g_ss.s1, g_ss.evF, 0);
    cudaStreamWaitEvent(g_ss.s2, g_ss.evF, 0);

    // chain A (s1): the GEMM (sole producer of g_hh)
    k_hsrc<<<(ni + 127) / 128, 256, smemB, g_ss.s1>>>(x_ing, W_ing, b_ing, ni);
    cudaEventRecord(g_ss.evA, g_ss.s1);

    // chain B (s2): prep -> a_dst, a_src matvecs (a_src no longer needs GEMM)
    k_prep<<<1, 256, 0, g_ss.s2>>>(W_taste, b_taste, att_dst, W_ing, b_ing, att_src);
    k_attvec<<<((nt + 7) / 8 + 7) / 8 + 1, 256, 0, g_ss.s2>>>(x_taste, nt, 0);
    k_attvec<<<((ni + 7) / 8 + 7) / 8 + 1, 256, 0, g_ss.s2>>>(x_ing, ni, 1);
    cudaEventRecord(g_ss.evB, g_ss.s2);

    // chain C (default): zero -> edge ranks -> scan -> (wait B) -> scatter
    int eb = (E_ + 255) / 256;
    int nb = (nt + SCAN_B - 1) / SCAN_B;
    k_zero<<<(nt + 255) / 256, 256>>>(nt);
    k_edge<<<eb, 256>>>(ei, E_, ni, nt);
    k_scan1<<<nb, SCAN_B>>>(nt);
    k_scan3<<<nb, SCAN_B>>>(nt, nb);
    cudaStreamWaitEvent(0, g_ss.evB, 0);
    k_scatter<<<eb, 256>>>(ei, E_, ni, nt);

    // join with GEMM, then aggregate + BN
    cudaStreamWaitEvent(0, g_ss.evA, 0);
    k_agg<<<(nt + 7) / 8, 256>>>(nt, gamma, beta, 1.0f / (float)nt);
    k_bn<<<(nt * 32 + 255) / 256, 256>>>(out, nt);
}

// round 16
// speedup vs baseline: 1.3683x; 1.3683x over previous
#include <cuda_runtime.h>
#include <cuda_fp16.h>
#include <mma.h>
#include <cstdint>

using namespace nvcuda;

#define H 128
#define NI_MAX 100000
#define NT_MAX 100000
#define E_MAX  800000
#define SCAN_B 1024
#define WLD 132      // epilogue C smem ld (floats)
#define WLDH 136     // W smem ld (halves)
#define XPADH 40     // x smem tile ld (halves)

// ---------------- scratch (device globals; no allocation allowed) ----------
__device__ uint2    g_hh[(size_t)NI_MAX * 32];   // h_src fp16 [NI,128]
__device__ uint2    g_aggh[(size_t)NT_MAX * 32]; // agg fp16 [NT,128]
__device__ float    g_asrc[NI_MAX];
__device__ float    g_adst[NT_MAX];
__device__ int      g_rank[E_MAX];             // per-edge rank within dst segment
__device__ int      g_cnt[NT_MAX];
__device__ int      g_off[NT_MAX];
__device__ int      g_itmp[NT_MAX];            // inclusive scan temp
__device__ int      g_bsum[256];
__device__ int2     g_edge[E_MAX];             // CSR payload {src, ev bits}
__device__ float4   g_wvd[32];                 // W_taste^T @ att_dst
__device__ float    g_cd[1];                   // b_taste . att_dst
__device__ float    g_csum[H];
__device__ float    g_csq[H];
__device__ float4   g_scale[32];
__device__ float4   g_shift[32];
__device__ int      g_tick[1];

// ---------------- host-side streams/events (created pre-main) --------------
struct SideStreams {
    cudaStream_t s1, s2;
    cudaEvent_t evF, evA, evB;
    SideStreams() {
        cudaStreamCreateWithFlags(&s1, cudaStreamNonBlocking);
        cudaStreamCreateWithFlags(&s2, cudaStreamNonBlocking);
        cudaEventCreateWithFlags(&evF, cudaEventDisableTiming);
        cudaEventCreateWithFlags(&evA, cudaEventDisableTiming);
        cudaEventCreateWithFlags(&evB, cudaEventDisableTiming);
    }
};
static SideStreams g_ss;

// ---------------- K0a: zero per-call state ---------------------------------
__global__ void k_zero(int nt) {
    int i = blockIdx.x * blockDim.x + threadIdx.x;
    if (i < nt) g_cnt[i] = 0;
    if (i < H) {
        g_csum[i] = 0.f;
        g_csq[i]  = 0.f;
    }
    if (i == 0) g_tick[0] = 0;
}

// ---------------- K0b: wv_dst = W_taste^T @ att_dst, c_dst = b.att ---------
__global__ void k_prep(const float* __restrict__ Wt_, const float* __restrict__ bt,
                       const float* __restrict__ attd) {
    __shared__ float sh[H];
    int t = threadIdx.x;                       // 128 threads
    float s = 0.f;
    #pragma unroll 8
    for (int k = 0; k < H; k++) s += Wt_[k * H + t] * attd[k];
    ((float*)g_wvd)[t] = s;
    sh[t] = bt[t] * attd[t];
    __syncthreads();
    for (int o = 64; o > 0; o >>= 1) {
        if (t < o) sh[t] += sh[t + o];
        __syncthreads();
    }
    if (t == 0) g_cd[0] = sh[0];
}

// ---------------- K2: a_dst = x_taste @ wv_dst + c_dst (8 nodes/warp) ------
__global__ void k_adst(const float* __restrict__ xt, int nt) {
    int wid  = blockIdx.x * (blockDim.x >> 5) + (threadIdx.x >> 5);
    int lane = threadIdx.x & 31;
    int t0 = wid * 8;
    if (t0 >= nt) return;
    float4 wv = g_wvd[lane];
    float d[8];
    #pragma unroll
    for (int j = 0; j < 8; j++) {
        int t = t0 + j;
        d[j] = 0.f;
        if (t < nt) {
            float4 v = ((const float4*)xt)[(size_t)t * 32 + lane];
            d[j] = v.x * wv.x + v.y * wv.y + v.z * wv.z + v.w * wv.w;
        }
    }
    #pragma unroll
    for (int o = 16; o > 0; o >>= 1) {
        #pragma unroll
        for (int j = 0; j < 8; j++)
            d[j] += __shfl_xor_sync(0xFFFFFFFFu, d[j], o);
    }
    if (lane == 0) {
        float cd = g_cd[0];
        #pragma unroll
        for (int j = 0; j < 8; j++)
            if (t0 + j < nt) g_adst[t0 + j] = d[j] + cd;
    }
}

// ---------------- K1: h = x @ W^T + b via FP16 wmma (chunked, dbl-buf) -----
__global__ __launch_bounds__(256, 2) void k_hsrc(
    const float* __restrict__ x, const float* __restrict__ W,
    const float* __restrict__ b, const float* __restrict__ att, int ni) {
    extern __shared__ float sm[];
    __half* smw = (__half*)sm;                 // W half: [col c][k] c*WLDH+k (34.8KB)
    __half* smx = (__half*)sm + H * WLDH;      // x half: [row][XPADH] (10.2KB)

    // stage W as half (coalesced read)
    for (int i = threadIdx.x; i < H * H / 2; i += 256) {
        float2 w2 = ((const float2*)W)[i];
        int c = (i * 2) >> 7, k = (i * 2) & 127;
        *(__half2*)(smw + c * WLDH + k) = __floats2half2_rn(w2.x, w2.y);
    }

    int warp = threadIdx.x >> 5;
    int lane = threadIdx.x & 31;
    int r0 = blockIdx.x * 128;
    if (r0 + 128 > ni) r0 = ni - 128;          // tail overlap
    int rloc = warp * 16;

    // chunk loader: 128 rows x 32 cols; 4 float4 per thread -> half2x2
    uint2 reg[4];
    #pragma unroll
    for (int i = 0; i < 4; i++) {
        int idx = threadIdx.x + i * 256;
        int row = idx >> 3, c4 = idx & 7;
        float4 v = *(const float4*)(x + (size_t)(r0 + row) * H + c4 * 4);
        __half2 h0 = __floats2half2_rn(v.x, v.y);
        __half2 h1 = __floats2half2_rn(v.z, v.w);
        reg[i].x = *reinterpret_cast<unsigned*>(&h0);
        reg[i].y = *reinterpret_cast<unsigned*>(&h1);
    }
    #pragma unroll
    for (int i = 0; i < 4; i++) {
        int idx = threadIdx.x + i * 256;
        int row = idx >> 3, c4 = idx & 7;
        *(uint2*)(smx + row * XPADH + c4 * 4) = reg[i];
    }
    __syncthreads();

    wmma::fragment<wmma::accumulator, 16, 16, 16, float> c[8];
    #pragma unroll
    for (int j = 0; j < 8; j++) wmma::fill_fragment(c[j], 0.f);

    for (int kc = 0; kc < 4; kc++) {
        if (kc < 3) {                           // prefetch next chunk
            #pragma unroll
            for (int i = 0; i < 4; i++) {
                int idx = threadIdx.x + i * 256;
                int row = idx >> 3, c4 = idx & 7;
                float4 v = *(const float4*)(x + (size_t)(r0 + row) * H + (kc + 1) * 32 + c4 * 4);
                __half2 h0 = __floats2half2_rn(v.x, v.y);
                __half2 h1 = __floats2half2_rn(v.z, v.w);
                reg[i].x = *reinterpret_cast<unsigned*>(&h0);
                reg[i].y = *reinterpret_cast<unsigned*>(&h1);
            }
        }
        #pragma unroll
        for (int kk = 0; kk < 32; kk += 16) {
            wmma::fragment<wmma::matrix_a, 16, 16, 16, __half, wmma::row_major> a;
            wmma::load_matrix_sync(a, smx + rloc * XPADH + kk, XPADH);
            #pragma unroll
            for (int j = 0; j < 8; j++) {
                wmma::fragment<wmma::matrix_b, 16, 16, 16, __half, wmma::col_major> bf;
                wmma::load_matrix_sync(bf, smw + (j * 16) * WLDH + kc * 32 + kk, WLDH);
                wmma::mma_sync(c[j], a, bf, c[j]);
            }
        }
        __syncthreads();
        if (kc < 3) {
            #pragma unroll
            for (int i = 0; i < 4; i++) {
                int idx = threadIdx.x + i * 256;
                int row = idx >> 3, c4 = idx & 7;
                *(uint2*)(smx + row * XPADH + c4 * 4) = reg[i];
            }
            __syncthreads();
        }
    }

    // epilogue: reuse whole smem as float [128][WLD]
    float* cs = sm + rloc * WLD;
    #pragma unroll
    for (int j = 0; j < 8; j++)
        wmma::store_matrix_sync(cs + j * 16, c[j], WLD, wmma::mem_row_major);
    __syncwarp();

    float4 bv = ((const float4*)b)[lane];
    float4 av = ((const float4*)att)[lane];
    for (int rr = 0; rr < 16; rr++) {
        int r = r0 + rloc + rr;
        float4 v = *(float4*)(cs + rr * WLD + lane * 4);
        v.x += bv.x; v.y += bv.y; v.z += bv.z; v.w += bv.w;
        __half2 p0 = __floats2half2_rn(v.x, v.y);
        __half2 p1 = __floats2half2_rn(v.z, v.w);
        uint2 pk;
        pk.x = *reinterpret_cast<unsigned*>(&p0);
        pk.y = *reinterpret_cast<unsigned*>(&p1);
        g_hh[(size_t)r * 32 + lane] = pk;
        float d = v.x * av.x + v.y * av.y + v.z * av.z + v.w * av.w;
        #pragma unroll
        for (int o = 16; o > 0; o >>= 1) d += __shfl_xor_sync(0xFFFFFFFFu, d, o);
        if (lane == 0) g_asrc[r] = d;
    }
}

// ---------------- K3: per-edge rank only (single atomic, no gathers) -------
__global__ void k_edge(const int* __restrict__ ei, int E_, int ni, int nt) {
    int e = blockIdx.x * blockDim.x + threadIdx.x;
    if (e >= E_) return;
    int s = ei[e];
    int d = ei[E_ + e];
    if ((unsigned)s >= (unsigned)ni || (unsigned)d >= (unsigned)nt) return;  // guard
    g_rank[e] = atomicAdd(&g_cnt[d], 1);
}

// ---------------- scan (counting-sort offsets) -----------------------------
__global__ void k_scan1(int n) {
    __shared__ int sh[SCAN_B];
    int i = blockIdx.x * SCAN_B + threadIdx.x;
    int v = (i < n) ? g_cnt[i] : 0;
    sh[threadIdx.x] = v;
    __syncthreads();
    for (int o = 1; o < SCAN_B; o <<= 1) {
        int t = (threadIdx.x >= o) ? sh[threadIdx.x - o] : 0;
        __syncthreads();
        sh[threadIdx.x] += t;
        __syncthreads();
    }
    if (i < n) g_itmp[i] = sh[threadIdx.x];
    if (threadIdx.x == SCAN_B - 1) g_bsum[blockIdx.x] = sh[threadIdx.x];
}
__global__ void k_scan3(int n, int nb) {
    __shared__ int sb[256];
    int t = threadIdx.x;
    if (t < 256) sb[t] = (t < nb) ? g_bsum[t] : 0;
    __syncthreads();
    for (int o = 1; o < 256; o <<= 1) {
        int x = 0;
        if (t < 256 && t >= o) x = sb[t - o];
        __syncthreads();
        if (t < 256) sb[t] += x;
        __syncthreads();
    }
    int boff = (blockIdx.x > 0) ? sb[blockIdx.x - 1] : 0;
    int i = blockIdx.x * SCAN_B + t;
    if (i < n) g_off[i] = g_itmp[i] - g_cnt[i] + boff;
}

// ---------------- K5: scatter into CSR; compute ev inline ------------------
__global__ void k_scatter(const int* __restrict__ ei, int E_, int ni, int nt) {
    int e = blockIdx.x * blockDim.x + threadIdx.x;
    if (e >= E_) return;
    int s = ei[e];
    int d = ei[E_ + e];
    if ((unsigned)s >= (unsigned)ni || (unsigned)d >= (unsigned)nt) return;  // guard
    float al = g_asrc[s] + g_adst[d];
    al = al > 0.f ? al : 0.2f * al;
    float ev = __expf(al);
    int pos = g_off[d] + g_rank[e];
    g_edge[pos] = make_int2(s, __float_as_int(ev));
}

// ---------------- K6: agg = relu(Σev·h / Σev) -> fp16; stats; BN prep ------
__global__ __launch_bounds__(256) void k_agg(int nt,
        const float* __restrict__ gamma, const float* __restrict__ beta, float invn) {
    __shared__ float bs[H], bq[H];
    __shared__ bool last;
    int tid  = threadIdx.x;
    if (tid < H) { bs[tid] = 0.f; bq[tid] = 0.f; }
    __syncthreads();

    int wid  = blockIdx.x * 8 + (tid >> 5);
    int lane = tid & 31;
    float4 acc = make_float4(0.f, 0.f, 0.f, 0.f);
    if (wid < nt) {
        int n = g_cnt[wid], off = g_off[wid];
        if (n > 0) {
            float den = 0.f;
            int2 pe = g_edge[off];
            uint2 p = g_hh[(size_t)pe.x * 32 + lane];
            for (int j = 0; j < n; j++) {
                int2 pe2 = make_int2(0, 0);
                uint2 p2 = make_uint2(0u, 0u);
                if (j + 1 < n) {
                    pe2 = g_edge[off + j + 1];
                    p2 = g_hh[(size_t)pe2.x * 32 + lane];   // issued before consume
                }
                __half2 h01 = *reinterpret_cast<__half2*>(&p.x);
                __half2 h23 = *reinterpret_cast<__half2*>(&p.y);
                float2 f01 = __half22float2(h01);
                float2 f23 = __half22float2(h23);
                float w = __int_as_float(pe.y);
                den += w;
                acc.x += w * f01.x; acc.y += w * f01.y;
                acc.z += w * f23.x; acc.w += w * f23.y;
                pe = pe2; p = p2;
            }
            float dinv = 1.0f / den;
            acc.x *= dinv; acc.y *= dinv; acc.z *= dinv; acc.w *= dinv;
        }
        acc.x = fmaxf(acc.x, 0.f); acc.y = fmaxf(acc.y, 0.f);
        acc.z = fmaxf(acc.z, 0.f); acc.w = fmaxf(acc.w, 0.f);
        __half2 p0 = __floats2half2_rn(acc.x, acc.y);
        __half2 p1 = __floats2half2_rn(acc.z, acc.w);
        uint2 pk;
        pk.x = *reinterpret_cast<unsigned*>(&p0);
        pk.y = *reinterpret_cast<unsigned*>(&p1);
        g_aggh[(size_t)wid * 32 + lane] = pk;
    }
    int c0 = lane * 4;
    atomicAdd(&bs[c0 + 0], acc.x); atomicAdd(&bs[c0 + 1], acc.y);
    atomicAdd(&bs[c0 + 2], acc.z); atomicAdd(&bs[c0 + 3], acc.w);
    atomicAdd(&bq[c0 + 0], acc.x * acc.x); atomicAdd(&bq[c0 + 1], acc.y * acc.y);
    atomicAdd(&bq[c0 + 2], acc.z * acc.z); atomicAdd(&bq[c0 + 3], acc.w * acc.w);
    __syncthreads();
    if (tid < H) {
        atomicAdd(&g_csum[tid], bs[tid]);
        atomicAdd(&g_csq[tid], bq[tid]);
    }
    __threadfence();
    if (tid == 0) last = (atomicAdd(&g_tick[0], 1) == gridDim.x - 1);
    __syncthreads();
    if (last && tid < H) {
        float mu  = g_csum[tid] * invn;
        float var = fmaxf(g_csq[tid] * invn - mu * mu, 0.f);
        float rs  = rsqrtf(var + 1e-5f);
        float sc  = gamma[tid] * rs;
        ((float*)g_scale)[tid] = sc;
        ((float*)g_shift)[tid] = beta[tid] - mu * sc;
    }
}

// ---------------- K9: out = relu(aggh*scale + shift) ------------------------
__global__ void k_bn(float* __restrict__ out, int nt) {
    int i = blockIdx.x * blockDim.x + threadIdx.x;     // (node,lane) index
    if (i >= nt * 32) return;
    int lane = i & 31;
    uint2 p = g_aggh[i];
    __half2 h01 = *reinterpret_cast<__half2*>(&p.x);
    __half2 h23 = *reinterpret_cast<__half2*>(&p.y);
    float2 f01 = __half22float2(h01);
    float2 f23 = __half22float2(h23);
    float4 sc = g_scale[lane];
    float4 sh = g_shift[lane];
    float4 v;
    v.x = fmaxf(f01.x * sc.x + sh.x, 0.f);
    v.y = fmaxf(f01.y * sc.y + sh.y, 0.f);
    v.z = fmaxf(f23.x * sc.z + sh.z, 0.f);
    v.w = fmaxf(f23.y * sc.w + sh.w, 0.f);
    ((float4*)out)[i] = v;
}

// ---------------- host -----------------------------------------------------
extern "C" void kernel_launch(void* const* d_in, const int* in_sizes, int n_in,
                              void* d_out, int out_size) {
    const float* x_ing   = (const float*)d_in[0];
    const float* x_taste = (const float*)d_in[1];
    const int*   ei      = (const int*)d_in[2];          // int32 edge index
    const float* W_ing   = (const float*)d_in[3];
    const float* b_ing   = (const float*)d_in[4];
    const float* W_taste = (const float*)d_in[5];
    const float* b_taste = (const float*)d_in[6];
    const float* att_src = (const float*)d_in[7];
    const float* att_dst = (const float*)d_in[8];
    // d_in[9..11] = k_lin_W, k_lin_b, q — unused (softmax over 1 metapath == 1.0)
    const float* gamma   = (const float*)d_in[12];
    const float* beta    = (const float*)d_in[13];

    int ni = in_sizes[0] / H;
    int nt = in_sizes[1] / H;
    int E_ = in_sizes[2] / 2;
    float* out = (float*)d_out;

    const int smemB = H * WLD * 4;   // 67.6 KB (fp32 epilogue; > fp16 staging 45KB)
    cudaFuncSetAttribute(k_hsrc, cudaFuncAttributeMaxDynamicSharedMemorySize, smemB);

    // fork: three independent chains overlap
    cudaEventRecord(g_ss.evF, 0);
    cudaStreamWaitEvent(g_ss.s1, g_ss.evF, 0);
    cudaStreamWaitEvent(g_ss.s2, g_ss.evF, 0);

    // chain A (s1): the GEMM
    k_hsrc<<<(ni + 127) / 128, 256, smemB, g_ss.s1>>>(x_ing, W_ing, b_ing, att_src, ni);
    cudaEventRecord(g_ss.evA, g_ss.s1);

    // chain B (s2): prep -> a_dst
    k_prep<<<1, 128, 0, g_ss.s2>>>(W_taste, b_taste, att_dst);
    k_adst<<<((nt + 7) / 8 + 7) / 8 + 1, 256, 0, g_ss.s2>>>(x_taste, nt);
    cudaEventRecord(g_ss.evB, g_ss.s2);

    // chain C (default): zero -> edge ranks -> scan
    int eb = (E_ + 255) / 256;
    int nb = (nt + SCAN_B - 1) / SCAN_B;
    k_zero<<<(nt + 255) / 256, 256>>>(nt);
    k_edge<<<eb, 256>>>(ei, E_, ni, nt);
    k_scan1<<<nb, SCAN_B>>>(nt);
    k_scan3<<<nb, SCAN_B>>>(nt, nb);

    // join: scatter needs asrc (A), adst (B), off/rank (C)
    cudaStreamWaitEvent(0, g_ss.evA, 0);
    cudaStreamWaitEvent(0, g_ss.evB, 0);

    k_scatter<<<eb, 256>>>(ei, E_, ni, nt);
    k_agg<<<(nt + 7) / 8, 256>>>(nt, gamma, beta, 1.0f / (float)nt);
    k_bn<<<(nt * 32 + 255) / 256, 256>>>(out, nt);
}

// round 17
// speedup vs baseline: 1.4049x; 1.0268x over previous
#include <cuda_runtime.h>
#include <cuda_fp16.h>
#include <mma.h>
#include <cstdint>

using namespace nvcuda;

#define H 128
#define NI_MAX 100000
#define NT_MAX 100000
#define E_MAX  800000
#define SCAN_B 1024
#define WLD 132      // epilogue C smem ld (floats)
#define WLDH 136     // W smem ld (halves)
#define XPADH 40     // x smem tile ld (halves)

// ---------------- scratch (device globals; no allocation allowed) ----------
__device__ uint2    g_hh[(size_t)NI_MAX * 32];   // h_src fp16 [NI,128]
__device__ uint2    g_aggh[(size_t)NT_MAX * 32]; // agg fp16 [NT,128]
__device__ float    g_asrc[NI_MAX];
__device__ float    g_adst[NT_MAX];
__device__ int      g_rank[E_MAX];             // per-edge rank within dst segment
__device__ int      g_cnt[NT_MAX];
__device__ int      g_off[NT_MAX];
__device__ int      g_itmp[NT_MAX];            // inclusive scan temp
__device__ int      g_bsum[256];
__device__ int      g_srcs[E_MAX];             // CSR payload: src id only
__device__ float4   g_wvd[32];                 // W_taste^T @ att_dst
__device__ float    g_cd[1];                   // b_taste . att_dst
__device__ float    g_csum[H];
__device__ float    g_csq[H];
__device__ float4   g_scale[32];
__device__ float4   g_shift[32];
__device__ int      g_tick[1];

// ---------------- host-side streams/events (created pre-main) --------------
struct SideStreams {
    cudaStream_t s1, s2;
    cudaEvent_t evF, evA, evB;
    SideStreams() {
        cudaStreamCreateWithFlags(&s1, cudaStreamNonBlocking);
        cudaStreamCreateWithFlags(&s2, cudaStreamNonBlocking);
        cudaEventCreateWithFlags(&evF, cudaEventDisableTiming);
        cudaEventCreateWithFlags(&evA, cudaEventDisableTiming);
        cudaEventCreateWithFlags(&evB, cudaEventDisableTiming);
    }
};
static SideStreams g_ss;

// ---------------- K0a: zero per-call state ---------------------------------
__global__ void k_zero(int nt) {
    int i = blockIdx.x * blockDim.x + threadIdx.x;
    if (i < nt) g_cnt[i] = 0;
    if (i < H) {
        g_csum[i] = 0.f;
        g_csq[i]  = 0.f;
    }
    if (i == 0) g_tick[0] = 0;
}

// ---------------- K0b: wv_dst = W_taste^T @ att_dst, c_dst = b.att ---------
__global__ void k_prep(const float* __restrict__ Wt_, const float* __restrict__ bt,
                       const float* __restrict__ attd) {
    __shared__ float sh[H];
    int t = threadIdx.x;                       // 128 threads
    float s = 0.f;
    #pragma unroll 8
    for (int k = 0; k < H; k++) s += Wt_[k * H + t] * attd[k];
    ((float*)g_wvd)[t] = s;
    sh[t] = bt[t] * attd[t];
    __syncthreads();
    for (int o = 64; o > 0; o >>= 1) {
        if (t < o) sh[t] += sh[t + o];
        __syncthreads();
    }
    if (t == 0) g_cd[0] = sh[0];
}

// ---------------- K2: a_dst = x_taste @ wv_dst + c_dst (8 nodes/warp) ------
__global__ void k_adst(const float* __restrict__ xt, int nt) {
    int wid  = blockIdx.x * (blockDim.x >> 5) + (threadIdx.x >> 5);
    int lane = threadIdx.x & 31;
    int t0 = wid * 8;
    if (t0 >= nt) return;
    float4 wv = g_wvd[lane];
    float d[8];
    #pragma unroll
    for (int j = 0; j < 8; j++) {
        int t = t0 + j;
        d[j] = 0.f;
        if (t < nt) {
            float4 v = ((const float4*)xt)[(size_t)t * 32 + lane];
            d[j] = v.x * wv.x + v.y * wv.y + v.z * wv.z + v.w * wv.w;
        }
    }
    #pragma unroll
    for (int o = 16; o > 0; o >>= 1) {
        #pragma unroll
        for (int j = 0; j < 8; j++)
            d[j] += __shfl_xor_sync(0xFFFFFFFFu, d[j], o);
    }
    if (lane == 0) {
        float cd = g_cd[0];
        #pragma unroll
        for (int j = 0; j < 8; j++)
            if (t0 + j < nt) g_adst[t0 + j] = d[j] + cd;
    }
}

// ---------------- K1: h = x @ W^T + b via FP16 wmma (chunked, dbl-buf) -----
__global__ __launch_bounds__(256, 2) void k_hsrc(
    const float* __restrict__ x, const float* __restrict__ W,
    const float* __restrict__ b, const float* __restrict__ att, int ni) {
    extern __shared__ float sm[];
    __half* smw = (__half*)sm;                 // W half: [col c][k] c*WLDH+k (34.8KB)
    __half* smx = (__half*)sm + H * WLDH;      // x half: [row][XPADH] (10.2KB)

    // stage W as half (coalesced read)
    for (int i = threadIdx.x; i < H * H / 2; i += 256) {
        float2 w2 = ((const float2*)W)[i];
        int c = (i * 2) >> 7, k = (i * 2) & 127;
        *(__half2*)(smw + c * WLDH + k) = __floats2half2_rn(w2.x, w2.y);
    }

    int warp = threadIdx.x >> 5;
    int lane = threadIdx.x & 31;
    int r0 = blockIdx.x * 128;
    if (r0 + 128 > ni) r0 = ni - 128;          // tail overlap
    int rloc = warp * 16;

    // chunk loader: 128 rows x 32 cols; 4 float4 per thread -> half2x2
    uint2 reg[4];
    #pragma unroll
    for (int i = 0; i < 4; i++) {
        int idx = threadIdx.x + i * 256;
        int row = idx >> 3, c4 = idx & 7;
        float4 v = *(const float4*)(x + (size_t)(r0 + row) * H + c4 * 4);
        __half2 h0 = __floats2half2_rn(v.x, v.y);
        __half2 h1 = __floats2half2_rn(v.z, v.w);
        reg[i].x = *reinterpret_cast<unsigned*>(&h0);
        reg[i].y = *reinterpret_cast<unsigned*>(&h1);
    }
    #pragma unroll
    for (int i = 0; i < 4; i++) {
        int idx = threadIdx.x + i * 256;
        int row = idx >> 3, c4 = idx & 7;
        *(uint2*)(smx + row * XPADH + c4 * 4) = reg[i];
    }
    __syncthreads();

    wmma::fragment<wmma::accumulator, 16, 16, 16, float> c[8];
    #pragma unroll
    for (int j = 0; j < 8; j++) wmma::fill_fragment(c[j], 0.f);

    for (int kc = 0; kc < 4; kc++) {
        if (kc < 3) {                           // prefetch next chunk
            #pragma unroll
            for (int i = 0; i < 4; i++) {
                int idx = threadIdx.x + i * 256;
                int row = idx >> 3, c4 = idx & 7;
                float4 v = *(const float4*)(x + (size_t)(r0 + row) * H + (kc + 1) * 32 + c4 * 4);
                __half2 h0 = __floats2half2_rn(v.x, v.y);
                __half2 h1 = __floats2half2_rn(v.z, v.w);
                reg[i].x = *reinterpret_cast<unsigned*>(&h0);
                reg[i].y = *reinterpret_cast<unsigned*>(&h1);
            }
        }
        #pragma unroll
        for (int kk = 0; kk < 32; kk += 16) {
            wmma::fragment<wmma::matrix_a, 16, 16, 16, __half, wmma::row_major> a;
            wmma::load_matrix_sync(a, smx + rloc * XPADH + kk, XPADH);
            #pragma unroll
            for (int j = 0; j < 8; j++) {
                wmma::fragment<wmma::matrix_b, 16, 16, 16, __half, wmma::col_major> bf;
                wmma::load_matrix_sync(bf, smw + (j * 16) * WLDH + kc * 32 + kk, WLDH);
                wmma::mma_sync(c[j], a, bf, c[j]);
            }
        }
        __syncthreads();
        if (kc < 3) {
            #pragma unroll
            for (int i = 0; i < 4; i++) {
                int idx = threadIdx.x + i * 256;
                int row = idx >> 3, c4 = idx & 7;
                *(uint2*)(smx + row * XPADH + c4 * 4) = reg[i];
            }
            __syncthreads();
        }
    }

    // epilogue: reuse whole smem as float [128][WLD]
    float* cs = sm + rloc * WLD;
    #pragma unroll
    for (int j = 0; j < 8; j++)
        wmma::store_matrix_sync(cs + j * 16, c[j], WLD, wmma::mem_row_major);
    __syncwarp();

    float4 bv = ((const float4*)b)[lane];
    float4 av = ((const float4*)att)[lane];
    for (int rr = 0; rr < 16; rr++) {
        int r = r0 + rloc + rr;
        float4 v = *(float4*)(cs + rr * WLD + lane * 4);
        v.x += bv.x; v.y += bv.y; v.z += bv.z; v.w += bv.w;
        __half2 p0 = __floats2half2_rn(v.x, v.y);
        __half2 p1 = __floats2half2_rn(v.z, v.w);
        uint2 pk;
        pk.x = *reinterpret_cast<unsigned*>(&p0);
        pk.y = *reinterpret_cast<unsigned*>(&p1);
        g_hh[(size_t)r * 32 + lane] = pk;
        float d = v.x * av.x + v.y * av.y + v.z * av.z + v.w * av.w;
        #pragma unroll
        for (int o = 16; o > 0; o >>= 1) d += __shfl_xor_sync(0xFFFFFFFFu, d, o);
        if (lane == 0) g_asrc[r] = d;
    }
}

// ---------------- K3: per-edge rank only (single atomic, no gathers) -------
__global__ void k_edge(const int* __restrict__ ei, int E_, int ni, int nt) {
    int e = blockIdx.x * blockDim.x + threadIdx.x;
    if (e >= E_) return;
    int s = ei[e];
    int d = ei[E_ + e];
    if ((unsigned)s >= (unsigned)ni || (unsigned)d >= (unsigned)nt) return;  // guard
    g_rank[e] = atomicAdd(&g_cnt[d], 1);
}

// ---------------- scan (counting-sort offsets) -----------------------------
__global__ void k_scan1(int n) {
    __shared__ int sh[SCAN_B];
    int i = blockIdx.x * SCAN_B + threadIdx.x;
    int v = (i < n) ? g_cnt[i] : 0;
    sh[threadIdx.x] = v;
    __syncthreads();
    for (int o = 1; o < SCAN_B; o <<= 1) {
        int t = (threadIdx.x >= o) ? sh[threadIdx.x - o] : 0;
        __syncthreads();
        sh[threadIdx.x] += t;
        __syncthreads();
    }
    if (i < n) g_itmp[i] = sh[threadIdx.x];
    if (threadIdx.x == SCAN_B - 1) g_bsum[blockIdx.x] = sh[threadIdx.x];
}
__global__ void k_scan3(int n, int nb) {
    __shared__ int sb[256];
    int t = threadIdx.x;
    if (t < 256) sb[t] = (t < nb) ? g_bsum[t] : 0;
    __syncthreads();
    for (int o = 1; o < 256; o <<= 1) {
        int x = 0;
        if (t < 256 && t >= o) x = sb[t - o];
        __syncthreads();
        if (t < 256) sb[t] += x;
        __syncthreads();
    }
    int boff = (blockIdx.x > 0) ? sb[blockIdx.x - 1] : 0;
    int i = blockIdx.x * SCAN_B + t;
    if (i < n) g_off[i] = g_itmp[i] - g_cnt[i] + boff;
}

// ---------------- K5: scatter src ids into CSR (no asrc/adst needed) -------
__global__ void k_scatter(const int* __restrict__ ei, int E_, int ni, int nt) {
    int e = blockIdx.x * blockDim.x + threadIdx.x;
    if (e >= E_) return;
    int s = ei[e];
    int d = ei[E_ + e];
    if ((unsigned)s >= (unsigned)ni || (unsigned)d >= (unsigned)nt) return;  // guard
    g_srcs[g_off[d] + g_rank[e]] = s;
}

// ---------------- K6: agg = relu(Σev·h / Σev), ev computed inline ----------
__global__ __launch_bounds__(256) void k_agg(int nt,
        const float* __restrict__ gamma, const float* __restrict__ beta, float invn) {
    __shared__ float bs[H], bq[H];
    __shared__ bool last;
    int tid  = threadIdx.x;
    if (tid < H) { bs[tid] = 0.f; bq[tid] = 0.f; }
    __syncthreads();

    int wid  = blockIdx.x * 8 + (tid >> 5);
    int lane = tid & 31;
    float4 acc = make_float4(0.f, 0.f, 0.f, 0.f);
    if (wid < nt) {
        int n = g_cnt[wid], off = g_off[wid];
        if (n > 0) {
            float ad = g_adst[wid];
            float den = 0.f;
            int s = g_srcs[off];
            float a = g_asrc[s];                        // warp-uniform broadcast
            uint2 p = g_hh[(size_t)s * 32 + lane];
            for (int j = 0; j < n; j++) {
                int s2 = 0; float a2 = 0.f;
                uint2 p2 = make_uint2(0u, 0u);
                if (j + 1 < n) {
                    s2 = g_srcs[off + j + 1];
                    a2 = g_asrc[s2];
                    p2 = g_hh[(size_t)s2 * 32 + lane];  // issued before consume
                }
                float al = a + ad;
                al = al > 0.f ? al : 0.2f * al;
                float w = __expf(al);
                __half2 h01 = *reinterpret_cast<__half2*>(&p.x);
                __half2 h23 = *reinterpret_cast<__half2*>(&p.y);
                float2 f01 = __half22float2(h01);
                float2 f23 = __half22float2(h23);
                den += w;
                acc.x += w * f01.x; acc.y += w * f01.y;
                acc.z += w * f23.x; acc.w += w * f23.y;
                s = s2; a = a2; p = p2;
            }
            float dinv = 1.0f / den;
            acc.x *= dinv; acc.y *= dinv; acc.z *= dinv; acc.w *= dinv;
        }
        acc.x = fmaxf(acc.x, 0.f); acc.y = fmaxf(acc.y, 0.f);
        acc.z = fmaxf(acc.z, 0.f); acc.w = fmaxf(acc.w, 0.f);
        __half2 p0 = __floats2half2_rn(acc.x, acc.y);
        __half2 p1 = __floats2half2_rn(acc.z, acc.w);
        uint2 pk;
        pk.x = *reinterpret_cast<unsigned*>(&p0);
        pk.y = *reinterpret_cast<unsigned*>(&p1);
        g_aggh[(size_t)wid * 32 + lane] = pk;
    }
    int c0 = lane * 4;
    atomicAdd(&bs[c0 + 0], acc.x); atomicAdd(&bs[c0 + 1], acc.y);
    atomicAdd(&bs[c0 + 2], acc.z); atomicAdd(&bs[c0 + 3], acc.w);
    atomicAdd(&bq[c0 + 0], acc.x * acc.x); atomicAdd(&bq[c0 + 1], acc.y * acc.y);
    atomicAdd(&bq[c0 + 2], acc.z * acc.z); atomicAdd(&bq[c0 + 3], acc.w * acc.w);
    __syncthreads();
    if (tid < H) {
        atomicAdd(&g_csum[tid], bs[tid]);
        atomicAdd(&g_csq[tid], bq[tid]);
    }
    __threadfence();
    if (tid == 0) last = (atomicAdd(&g_tick[0], 1) == gridDim.x - 1);
    __syncthreads();
    if (last && tid < H) {
        float mu  = g_csum[tid] * invn;
        float var = fmaxf(g_csq[tid] * invn - mu * mu, 0.f);
        float rs  = rsqrtf(var + 1e-5f);
        float sc  = gamma[tid] * rs;
        ((float*)g_scale)[tid] = sc;
        ((float*)g_shift)[tid] = beta[tid] - mu * sc;
    }
}

// ---------------- K9: out = relu(aggh*scale + shift) ------------------------
__global__ void k_bn(float* __restrict__ out, int nt) {
    int i = blockIdx.x * blockDim.x + threadIdx.x;     // (node,lane) index
    if (i >= nt * 32) return;
    int lane = i & 31;
    uint2 p = g_aggh[i];
    __half2 h01 = *reinterpret_cast<__half2*>(&p.x);
    __half2 h23 = *reinterpret_cast<__half2*>(&p.y);
    float2 f01 = __half22float2(h01);
    float2 f23 = __half22float2(h23);
    float4 sc = g_scale[lane];
    float4 sh = g_shift[lane];
    float4 v;
    v.x = fmaxf(f01.x * sc.x + sh.x, 0.f);
    v.y = fmaxf(f01.y * sc.y + sh.y, 0.f);
    v.z = fmaxf(f23.x * sc.z + sh.z, 0.f);
    v.w = fmaxf(f23.y * sc.w + sh.w, 0.f);
    ((float4*)out)[i] = v;
}

// ---------------- host -----------------------------------------------------
extern "C" void kernel_launch(void* const* d_in, const int* in_sizes, int n_in,
                              void* d_out, int out_size) {
    const float* x_ing   = (const float*)d_in[0];
    const float* x_taste = (const float*)d_in[1];
    const int*   ei      = (const int*)d_in[2];          // int32 edge index
    const float* W_ing   = (const float*)d_in[3];
    const float* b_ing   = (const float*)d_in[4];
    const float* W_taste = (const float*)d_in[5];
    const float* b_taste = (const float*)d_in[6];
    const float* att_src = (const float*)d_in[7];
    const float* att_dst = (const float*)d_in[8];
    // d_in[9..11] = k_lin_W, k_lin_b, q — unused (softmax over 1 metapath == 1.0)
    const float* gamma   = (const float*)d_in[12];
    const float* beta    = (const float*)d_in[13];

    int ni = in_sizes[0] / H;
    int nt = in_sizes[1] / H;
    int E_ = in_sizes[2] / 2;
    float* out = (float*)d_out;

    const int smemB = H * WLD * 4;   // 67.6 KB
    cudaFuncSetAttribute(k_hsrc, cudaFuncAttributeMaxDynamicSharedMemorySize, smemB);

    // fork: three independent chains overlap
    cudaEventRecord(g_ss.evF, 0);
    cudaStreamWaitEvent(g_ss.s1, g_ss.evF, 0);
    cudaStreamWaitEvent(g_ss.s2, g_ss.evF, 0);

    // chain A (s1): the GEMM (g_hh + asrc)
    k_hsrc<<<(ni + 127) / 128, 256, smemB, g_ss.s1>>>(x_ing, W_ing, b_ing, att_src, ni);
    cudaEventRecord(g_ss.evA, g_ss.s1);

    // chain B (s2): prep -> a_dst
    k_prep<<<1, 128, 0, g_ss.s2>>>(W_taste, b_taste, att_dst);
    k_adst<<<((nt + 7) / 8 + 7) / 8 + 1, 256, 0, g_ss.s2>>>(x_taste, nt);
    cudaEventRecord(g_ss.evB, g_ss.s2);

    // chain C (default): zero -> edge ranks -> scan -> scatter (src only;
    // needs nothing from A or B, so it all overlaps the GEMM)
    int eb = (E_ + 255) / 256;
    int nb = (nt + SCAN_B - 1) / SCAN_B;
    k_zero<<<(nt + 255) / 256, 256>>>(nt);
    k_edge<<<eb, 256>>>(ei, E_, ni, nt);
    k_scan1<<<nb, SCAN_B>>>(nt);
    k_scan3<<<nb, SCAN_B>>>(nt, nb);
    k_scatter<<<eb, 256>>>(ei, E_, ni, nt);

    // join: agg needs g_hh+asrc (A), adst (B), CSR (C)
    cudaStreamWaitEvent(0, g_ss.evA, 0);
    cudaStreamWaitEvent(0, g_ss.evB, 0);

    k_agg<<<(nt + 7) / 8, 256>>>(nt, gamma, beta, 1.0f / (float)nt);
    k_bn<<<(nt * 32 + 255) / 256, 256>>>(out, nt);
}